// round 1
// baseline (speedup 1.0000x reference)
#include <cuda_runtime.h>
#include <cstdint>

// Problem constants
#define BDIM 256      // batch
#define EDIM 4096     // number of codes
#define KDIM 16384    // embedding dim (32*8*8*8)

// Tiling
#define BM 64
#define BN 64
#define BK 32

__device__ unsigned long long g_best[BDIM];

// ---------------------------------------------------------------------------
// Kernel 1: zero output, reset per-batch best
// ---------------------------------------------------------------------------
__global__ void vq_init_kernel(float* __restrict__ out) {
    int i = blockIdx.x * blockDim.x + threadIdx.x;
    int stride = gridDim.x * blockDim.x;
    const int total = BDIM * EDIM;
    for (int idx = i; idx < total; idx += stride) out[idx] = 0.0f;
    if (i < BDIM) g_best[i] = 0xFFFFFFFFFFFFFFFFULL;
}

// ordered-uint transform: preserves float ordering under unsigned compare
__device__ __forceinline__ unsigned int ordered_float(float f) {
    unsigned int u = __float_as_uint(f);
    return (u & 0x80000000u) ? ~u : (u | 0x80000000u);
}

// ---------------------------------------------------------------------------
// Kernel 2: tiled GEMM (dot products) + fused ||e||^2 + per-CTA argmin merge
// Grid: (EDIM/BN, BDIM/BM) = (64, 4); 256 threads
// ---------------------------------------------------------------------------
__global__ __launch_bounds__(256)
void vq_main_kernel(const float* __restrict__ A,   // [BDIM, KDIM] inputs
                    const float* __restrict__ W)   // [EDIM, KDIM] codebook
{
    __shared__ float As[BK][BM];
    __shared__ float Bs[BK][BN];
    __shared__ float esq_sh[BN];
    __shared__ unsigned long long best_sh[BM];

    const int tid = threadIdx.x;
    const int bn0 = blockIdx.x * BN;   // code tile base
    const int bm0 = blockIdx.y * BM;   // batch tile base

    const int tx = tid & 15;           // 0..15 -> 4 codes each
    const int ty = tid >> 4;           // 0..15 -> 4 batch rows each

    // Load mapping: each thread loads rows (lrow, lrow+32) x 4 k-floats at kq
    const int lrow = tid >> 3;         // 0..31
    const int kq   = (tid & 7) * 4;    // 0,4,...,28

    if (tid < BN) esq_sh[tid] = 0.0f;
    if (tid < BM) best_sh[tid] = 0xFFFFFFFFFFFFFFFFULL;

    float acc[4][4];
#pragma unroll
    for (int i = 0; i < 4; i++)
#pragma unroll
        for (int j = 0; j < 4; j++) acc[i][j] = 0.0f;

    float esq0 = 0.0f, esq1 = 0.0f;

    const float* Aptr = A + (size_t)bm0 * KDIM;
    const float* Bptr = W + (size_t)bn0 * KDIM;

    for (int k0 = 0; k0 < KDIM; k0 += BK) {
        // Global loads (float4, coalesced: 8 threads cover 128B of one row)
        float4 a0 = *(const float4*)(Aptr + (size_t)lrow        * KDIM + k0 + kq);
        float4 a1 = *(const float4*)(Aptr + (size_t)(lrow + 32) * KDIM + k0 + kq);
        float4 b0 = *(const float4*)(Bptr + (size_t)lrow        * KDIM + k0 + kq);
        float4 b1 = *(const float4*)(Bptr + (size_t)(lrow + 32) * KDIM + k0 + kq);

        __syncthreads();   // previous iteration's smem reads complete

        As[kq + 0][lrow] = a0.x; As[kq + 1][lrow] = a0.y;
        As[kq + 2][lrow] = a0.z; As[kq + 3][lrow] = a0.w;
        As[kq + 0][lrow + 32] = a1.x; As[kq + 1][lrow + 32] = a1.y;
        As[kq + 2][lrow + 32] = a1.z; As[kq + 3][lrow + 32] = a1.w;

        Bs[kq + 0][lrow] = b0.x; Bs[kq + 1][lrow] = b0.y;
        Bs[kq + 2][lrow] = b0.z; Bs[kq + 3][lrow] = b0.w;
        Bs[kq + 0][lrow + 32] = b1.x; Bs[kq + 1][lrow + 32] = b1.y;
        Bs[kq + 2][lrow + 32] = b1.z; Bs[kq + 3][lrow + 32] = b1.w;

        // fused ||e||^2 partials (each codebook element loaded exactly once)
        esq0 += b0.x * b0.x + b0.y * b0.y + b0.z * b0.z + b0.w * b0.w;
        esq1 += b1.x * b1.x + b1.y * b1.y + b1.z * b1.z + b1.w * b1.w;

        __syncthreads();

#pragma unroll
        for (int kk = 0; kk < BK; kk++) {
            float a[4], b[4];
            *(float4*)a = *(const float4*)&As[kk][ty * 4];
            *(float4*)b = *(const float4*)&Bs[kk][tx * 4];
#pragma unroll
            for (int i = 0; i < 4; i++)
#pragma unroll
                for (int j = 0; j < 4; j++)
                    acc[i][j] = fmaf(a[i], b[j], acc[i][j]);
        }
    }

    // Reduce ||e||^2 across the 8 threads that covered each code row
    atomicAdd(&esq_sh[lrow],      esq0);
    atomicAdd(&esq_sh[lrow + 32], esq1);
    __syncthreads();

    // key(b,e) = ||e||^2 - 2 * dot  (||x||^2 is argmin-invariant).
    // Pack (ordered_key << 32) | code_idx: atomicMin gives global argmin with
    // ties resolved to smallest index (matches jnp.argmin first-occurrence).
#pragma unroll
    for (int i = 0; i < 4; i++) {
        const int brow = ty * 4 + i;
        unsigned long long local = 0xFFFFFFFFFFFFFFFFULL;
#pragma unroll
        for (int j = 0; j < 4; j++) {
            float key = esq_sh[tx * 4 + j] - 2.0f * acc[i][j];
            unsigned long long p =
                ((unsigned long long)ordered_float(key) << 32) |
                (unsigned int)(bn0 + tx * 4 + j);
            local = (p < local) ? p : local;
        }
        atomicMin(&best_sh[brow], local);
    }
    __syncthreads();

    if (tid < BM) atomicMin(&g_best[bm0 + tid], best_sh[tid]);
}

// ---------------------------------------------------------------------------
// Kernel 3: scatter the one-hot 1.0
// ---------------------------------------------------------------------------
__global__ void vq_writeout_kernel(float* __restrict__ out) {
    int b = threadIdx.x;
    if (b < BDIM) {
        unsigned long long p = g_best[b];
        int idx = (int)(p & 0xFFFFFFFFu);
        out[(size_t)b * EDIM + idx] = 1.0f;
    }
}

// ---------------------------------------------------------------------------
extern "C" void kernel_launch(void* const* d_in, const int* in_sizes, int n_in,
                              void* d_out, int out_size) {
    const float* inputs = (const float*)d_in[0];   // [256, 16384]
    const float* codes  = (const float*)d_in[1];   // [4096, 16384]
    float* out = (float*)d_out;                    // [256, 4096]

    vq_init_kernel<<<512, 256>>>(out);

    dim3 grid(EDIM / BN, BDIM / BM);   // (64, 4)
    vq_main_kernel<<<grid, 256>>>(inputs, codes);

    vq_writeout_kernel<<<1, 256>>>(out);
}

// round 2
// speedup vs baseline: 1.0076x; 1.0076x over previous
#include <cuda_runtime.h>
#include <cstdint>

// Problem constants
#define BDIM 256      // batch
#define EDIM 4096     // number of codes
#define KDIM 16384    // embedding dim (32*8*8*8)

// Tiling
#define BM 64
#define BN 64
#define BK 32

__device__ unsigned long long g_best[BDIM];

// ---------------------------------------------------------------------------
// Kernel 1: zero output, reset per-batch best
// ---------------------------------------------------------------------------
__global__ void vq_init_kernel(float* __restrict__ out) {
    int i = blockIdx.x * blockDim.x + threadIdx.x;
    int stride = gridDim.x * blockDim.x;
    const int total = BDIM * EDIM;
    for (int idx = i; idx < total; idx += stride) out[idx] = 0.0f;
    if (i < BDIM) g_best[i] = 0xFFFFFFFFFFFFFFFFULL;
}

// ordered-uint transform: preserves float ordering under unsigned compare
__device__ __forceinline__ unsigned int ordered_float(float f) {
    unsigned int u = __float_as_uint(f);
    return (u & 0x80000000u) ? ~u : (u | 0x80000000u);
}

// ---------------------------------------------------------------------------
// Kernel 2: tiled GEMM (dot products) + fused ||e||^2 + per-CTA argmin merge
// Grid: (EDIM/BN, BDIM/BM) = (64, 4); 256 threads
// ---------------------------------------------------------------------------
__global__ __launch_bounds__(256)
void vq_main_kernel(const float* __restrict__ A,   // [BDIM, KDIM] inputs
                    const float* __restrict__ W)   // [EDIM, KDIM] codebook
{
    __shared__ float As[BK][BM];
    __shared__ float Bs[BK][BN];
    __shared__ float esq_sh[BN];
    __shared__ unsigned long long best_sh[BM];

    const int tid = threadIdx.x;
    const int bn0 = blockIdx.x * BN;   // code tile base
    const int bm0 = blockIdx.y * BM;   // batch tile base

    const int tx = tid & 15;           // 0..15 -> 4 codes each
    const int ty = tid >> 4;           // 0..15 -> 4 batch rows each

    // Load mapping: each thread loads rows (lrow, lrow+32) x 4 k-floats at kq
    const int lrow = tid >> 3;         // 0..31
    const int kq   = (tid & 7) * 4;    // 0,4,...,28

    if (tid < BN) esq_sh[tid] = 0.0f;
    if (tid < BM) best_sh[tid] = 0xFFFFFFFFFFFFFFFFULL;

    float acc[4][4];
#pragma unroll
    for (int i = 0; i < 4; i++)
#pragma unroll
        for (int j = 0; j < 4; j++) acc[i][j] = 0.0f;

    float esq0 = 0.0f, esq1 = 0.0f;

    const float* Aptr = A + (size_t)bm0 * KDIM;
    const float* Bptr = W + (size_t)bn0 * KDIM;

    for (int k0 = 0; k0 < KDIM; k0 += BK) {
        // Global loads (float4, coalesced: 8 threads cover 128B of one row)
        float4 a0 = *(const float4*)(Aptr + (size_t)lrow        * KDIM + k0 + kq);
        float4 a1 = *(const float4*)(Aptr + (size_t)(lrow + 32) * KDIM + k0 + kq);
        float4 b0 = *(const float4*)(Bptr + (size_t)lrow        * KDIM + k0 + kq);
        float4 b1 = *(const float4*)(Bptr + (size_t)(lrow + 32) * KDIM + k0 + kq);

        __syncthreads();   // previous iteration's smem reads complete

        As[kq + 0][lrow] = a0.x; As[kq + 1][lrow] = a0.y;
        As[kq + 2][lrow] = a0.z; As[kq + 3][lrow] = a0.w;
        As[kq + 0][lrow + 32] = a1.x; As[kq + 1][lrow + 32] = a1.y;
        As[kq + 2][lrow + 32] = a1.z; As[kq + 3][lrow + 32] = a1.w;

        Bs[kq + 0][lrow] = b0.x; Bs[kq + 1][lrow] = b0.y;
        Bs[kq + 2][lrow] = b0.z; Bs[kq + 3][lrow] = b0.w;
        Bs[kq + 0][lrow + 32] = b1.x; Bs[kq + 1][lrow + 32] = b1.y;
        Bs[kq + 2][lrow + 32] = b1.z; Bs[kq + 3][lrow + 32] = b1.w;

        // fused ||e||^2 partials (each codebook element loaded exactly once)
        esq0 += b0.x * b0.x + b0.y * b0.y + b0.z * b0.z + b0.w * b0.w;
        esq1 += b1.x * b1.x + b1.y * b1.y + b1.z * b1.z + b1.w * b1.w;

        __syncthreads();

#pragma unroll
        for (int kk = 0; kk < BK; kk++) {
            float a[4], b[4];
            *(float4*)a = *(const float4*)&As[kk][ty * 4];
            *(float4*)b = *(const float4*)&Bs[kk][tx * 4];
#pragma unroll
            for (int i = 0; i < 4; i++)
#pragma unroll
                for (int j = 0; j < 4; j++)
                    acc[i][j] = fmaf(a[i], b[j], acc[i][j]);
        }
    }

    // Reduce ||e||^2 across the 8 threads that covered each code row
    atomicAdd(&esq_sh[lrow],      esq0);
    atomicAdd(&esq_sh[lrow + 32], esq1);
    __syncthreads();

    // key(b,e) = ||e||^2 - 2 * dot  (||x||^2 is argmin-invariant).
    // Pack (ordered_key << 32) | code_idx: atomicMin gives global argmin with
    // ties resolved to smallest index (matches jnp.argmin first-occurrence).
#pragma unroll
    for (int i = 0; i < 4; i++) {
        const int brow = ty * 4 + i;
        unsigned long long local = 0xFFFFFFFFFFFFFFFFULL;
#pragma unroll
        for (int j = 0; j < 4; j++) {
            float key = esq_sh[tx * 4 + j] - 2.0f * acc[i][j];
            unsigned long long p =
                ((unsigned long long)ordered_float(key) << 32) |
                (unsigned int)(bn0 + tx * 4 + j);
            local = (p < local) ? p : local;
        }
        atomicMin(&best_sh[brow], local);
    }
    __syncthreads();

    if (tid < BM) atomicMin(&g_best[bm0 + tid], best_sh[tid]);
}

// ---------------------------------------------------------------------------
// Kernel 3: scatter the one-hot 1.0
// ---------------------------------------------------------------------------
__global__ void vq_writeout_kernel(float* __restrict__ out) {
    int b = threadIdx.x;
    if (b < BDIM) {
        unsigned long long p = g_best[b];
        int idx = (int)(p & 0xFFFFFFFFu);
        out[(size_t)b * EDIM + idx] = 1.0f;
    }
}

// ---------------------------------------------------------------------------
extern "C" void kernel_launch(void* const* d_in, const int* in_sizes, int n_in,
                              void* d_out, int out_size) {
    const float* inputs = (const float*)d_in[0];   // [256, 16384]
    const float* codes  = (const float*)d_in[1];   // [4096, 16384]
    float* out = (float*)d_out;                    // [256, 4096]

    vq_init_kernel<<<512, 256>>>(out);

    dim3 grid(EDIM / BN, BDIM / BM);   // (64, 4)
    vq_main_kernel<<<grid, 256>>>(inputs, codes);

    vq_writeout_kernel<<<1, 256>>>(out);
}

// round 5
// speedup vs baseline: 5.3627x; 5.3223x over previous
#include <cuda_runtime.h>
#include <cstdint>

// ---------------------------------------------------------------------------
// Problem constants
// ---------------------------------------------------------------------------
#define BDIM 256      // batch rows
#define EDIM 4096     // codes
#define KDIM 16384    // embedding dim

// GEMM tiling
#define BM 128        // batch rows per CTA
#define BN 64         // codes per CTA
#define BK 64         // k per stage (64 bf16 = 128 B = one SW128 row)
#define NCHUNK (KDIM / BK)                    // 256
#define A_BYTES (BM * BK * 2)                 // 16384
#define B_BYTES (BN * BK * 2)                 // 8192
#define STAGE_BYTES (A_BYTES + B_BYTES)       // 24576
#define DYN_SMEM (2 * STAGE_BYTES + 256)      // 49408 (needs attr opt-in)

#define MARGIN 12.0f

__device__ unsigned long long g_best[BDIM];
__device__ float g_keys[BDIM * EDIM];         // approx keys workspace (4 MB)

// ---------------------------------------------------------------------------
// Helpers
// ---------------------------------------------------------------------------
__device__ __forceinline__ uint32_t smem_u32(const void* p) {
    uint32_t a;
    asm("{ .reg .u64 t; cvta.to.shared.u64 t, %1; cvt.u32.u64 %0, t; }" : "=r"(a) : "l"(p));
    return a;
}

#define SW128(o) ((o) ^ (((o) >> 3) & 0x70))

__device__ __forceinline__ unsigned int ordered_float(float f) {
    unsigned int u = __float_as_uint(f);
    return (u & 0x80000000u) ? ~u : (u | 0x80000000u);
}
__device__ __forceinline__ float inv_ordered(unsigned int o) {
    unsigned int u = (o & 0x80000000u) ? (o ^ 0x80000000u) : ~o;
    return __uint_as_float(u);
}

// pack two fp32 -> bf16x2 (lo in low half)
__device__ __forceinline__ uint32_t pk_bf2(float lo, float hi) {
    uint32_t r;
    asm("cvt.rn.bf16x2.f32 %0, %1, %2;" : "=r"(r) : "f"(hi), "f"(lo));
    return r;
}

__device__ __forceinline__ void ldsm4(uint32_t* r, uint32_t addr) {
    asm volatile("ldmatrix.sync.aligned.m8n8.x4.shared.b16 {%0,%1,%2,%3}, [%4];"
                 : "=r"(r[0]), "=r"(r[1]), "=r"(r[2]), "=r"(r[3]) : "r"(addr));
}

__device__ __forceinline__ void sts128(uint32_t addr, uint32_t d0, uint32_t d1,
                                       uint32_t d2, uint32_t d3) {
    asm volatile("st.shared.v4.b32 [%0], {%1,%2,%3,%4};"
                 :: "r"(addr), "r"(d0), "r"(d1), "r"(d2), "r"(d3) : "memory");
}

__device__ __forceinline__ void mma16816(float* d, const uint32_t* a,
                                         uint32_t b0, uint32_t b1) {
    asm volatile("mma.sync.aligned.m16n8k16.row.col.f32.bf16.bf16.f32 "
                 "{%0,%1,%2,%3}, {%4,%5,%6,%7}, {%8,%9}, {%0,%1,%2,%3};"
                 : "+f"(d[0]), "+f"(d[1]), "+f"(d[2]), "+f"(d[3])
                 : "r"(a[0]), "r"(a[1]), "r"(a[2]), "r"(a[3]), "r"(b0), "r"(b1));
}

// ---------------------------------------------------------------------------
// Kernel 1: init — zero one-hot output, reset per-row best
// ---------------------------------------------------------------------------
__global__ void vq_init_kernel(float4* __restrict__ out4) {
    int i = blockIdx.x * blockDim.x + threadIdx.x;   // BDIM*EDIM/4 threads
    out4[i] = make_float4(0.f, 0.f, 0.f, 0.f);
    if (i < BDIM) g_best[i] = 0xFFFFFFFFFFFFFFFFULL;
}

// ---------------------------------------------------------------------------
// Kernel 2: bf16 mma.sync GEMM (on-the-fly fp32->bf16) + fused ||e||^2
//           + approx keys + approx argmin
// grid (EDIM/BN, BDIM/BM) = (64, 2); 256 threads (8 warps of 32x32 tiles)
// ---------------------------------------------------------------------------
__global__ __launch_bounds__(256, 1)
void vq_main_kernel(const float* __restrict__ A,   // [BDIM, KDIM]
                    const float* __restrict__ W)   // [EDIM, KDIM]
{
    extern __shared__ char dynraw[];
    __shared__ float esq_sh[BN];
    __shared__ unsigned long long best_sh[BM];

    const int t    = threadIdx.x;
    const int lane = t & 31;
    const int wid  = t >> 5;
    const int bn0  = blockIdx.x * BN;
    const int bm0  = blockIdx.y * BM;
    const int wm   = (wid & 3) * 32;   // warp M offset in tile
    const int wn   = (wid >> 2) * 32;  // warp N offset in tile

    // 128B-align the dynamic region so SW128 bank math holds
    const uint32_t rawb  = smem_u32(dynraw);
    const uint32_t sbase = (rawb + 127u) & ~127u;

    if (t < BM) best_sh[t] = 0xFFFFFFFFFFFFFFFFULL;

    float acc[2][4][4];
#pragma unroll
    for (int im = 0; im < 2; im++)
#pragma unroll
        for (int in = 0; in < 4; in++)
#pragma unroll
            for (int q = 0; q < 4; q++) acc[im][in][q] = 0.0f;

    float esq0 = 0.0f, esq1 = 0.0f;

    const int r8   = t >> 3;      // base row index (0..31)
    const int acol = t & 7;       // 8-float chunk column

    float4 ra[8];                 // A prefetch: 4 rows x 2 float4
    float4 rb[4];                 // B prefetch: 2 rows x 2 float4

    const float* Abase = A + (size_t)bm0 * KDIM;
    const float* Bbase = W + (size_t)bn0 * KDIM;

    // ---- prologue: prefetch chunk 0 ----
    {
        const float* Ac = Abase + acol * 8;
        const float* Bc = Bbase + acol * 8;
#pragma unroll
        for (int i = 0; i < 4; i++) {
            const float4* p = (const float4*)(Ac + (size_t)(r8 + i * 32) * KDIM);
            ra[2 * i] = p[0]; ra[2 * i + 1] = p[1];
        }
#pragma unroll
        for (int i = 0; i < 2; i++) {
            const float4* p = (const float4*)(Bc + (size_t)(r8 + i * 32) * KDIM);
            rb[2 * i] = p[0]; rb[2 * i + 1] = p[1];
        }
    }

    for (int c = 0; c < NCHUNK; c++) {
        const uint32_t sA = sbase + (uint32_t)(c & 1) * STAGE_BYTES;
        const uint32_t sB = sA + A_BYTES;

        // ---- convert + store current regs to smem stage ----
#pragma unroll
        for (int i = 0; i < 4; i++) {
            const int r = r8 + i * 32;
            const float4 v0 = ra[2 * i], v1 = ra[2 * i + 1];
            uint32_t off = (uint32_t)(r * 128 + acol * 16);
            sts128(sA + SW128(off),
                   pk_bf2(v0.x, v0.y), pk_bf2(v0.z, v0.w),
                   pk_bf2(v1.x, v1.y), pk_bf2(v1.z, v1.w));
        }
#pragma unroll
        for (int i = 0; i < 2; i++) {
            const int r = r8 + i * 32;
            const float4 v0 = rb[2 * i], v1 = rb[2 * i + 1];
            float s = v0.x * v0.x + v0.y * v0.y + v0.z * v0.z + v0.w * v0.w
                    + v1.x * v1.x + v1.y * v1.y + v1.z * v1.z + v1.w * v1.w;
            if (i == 0) esq0 += s; else esq1 += s;
            uint32_t off = (uint32_t)(r * 128 + acol * 16);
            sts128(sB + SW128(off),
                   pk_bf2(v0.x, v0.y), pk_bf2(v0.z, v0.w),
                   pk_bf2(v1.x, v1.y), pk_bf2(v1.z, v1.w));
        }

        // ---- prefetch next chunk (hidden under sync + mma) ----
        if (c + 1 < NCHUNK) {
            const float* Ac = Abase + (size_t)(c + 1) * BK + acol * 8;
            const float* Bc = Bbase + (size_t)(c + 1) * BK + acol * 8;
#pragma unroll
            for (int i = 0; i < 4; i++) {
                const float4* p = (const float4*)(Ac + (size_t)(r8 + i * 32) * KDIM);
                ra[2 * i] = p[0]; ra[2 * i + 1] = p[1];
            }
#pragma unroll
            for (int i = 0; i < 2; i++) {
                const float4* p = (const float4*)(Bc + (size_t)(r8 + i * 32) * KDIM);
                rb[2 * i] = p[0]; rb[2 * i + 1] = p[1];
            }
        }

        __syncthreads();

        // ---- compute: 4 x k16 steps over this stage ----
#pragma unroll
        for (int ks = 0; ks < 4; ks++) {
            uint32_t afr[2][4], bfr[2][4];
#pragma unroll
            for (int im = 0; im < 2; im++) {
                const int row = wm + im * 16 + (lane & 15);
                uint32_t off = (uint32_t)(row * 128 + ks * 32 + (lane >> 4) * 16);
                ldsm4(afr[im], sA + SW128(off));
            }
#pragma unroll
            for (int j = 0; j < 2; j++) {
                const int row = wn + 16 * j + (lane & 7) + ((lane >> 4) & 1) * 8;
                uint32_t off = (uint32_t)(row * 128 + ks * 32 + ((lane >> 3) & 1) * 16);
                ldsm4(bfr[j], sB + SW128(off));
            }
#pragma unroll
            for (int im = 0; im < 2; im++)
#pragma unroll
                for (int in = 0; in < 4; in++)
                    mma16816(acc[im][in], afr[im],
                             bfr[in >> 1][(in & 1) * 2],
                             bfr[in >> 1][(in & 1) * 2 + 1]);
        }
        // note: next iteration's STS targets the OTHER buffer; the barrier
        // above (passed by all) guarantees stage c&1 was fully written, and
        // the barrier of iteration c+1 protects stage (c&1) from iter c+2.
    }

    // ---- esq reduction: 8 threads share each B row ----
#pragma unroll
    for (int o = 4; o; o >>= 1) {
        esq0 += __shfl_xor_sync(0xffffffffu, esq0, o);
        esq1 += __shfl_xor_sync(0xffffffffu, esq1, o);
    }
    if ((t & 7) == 0) { esq_sh[r8] = esq0; esq_sh[r8 + 32] = esq1; }
    __syncthreads();

    // ---- epilogue: approx keys + per-row packed argmin ----
#pragma unroll
    for (int im = 0; im < 2; im++) {
#pragma unroll
        for (int qh = 0; qh < 2; qh++) {
            const int m = wm + im * 16 + qh * 8 + (lane >> 2);
            unsigned long long best = 0xFFFFFFFFFFFFFFFFULL;
            float* krow = g_keys + (size_t)(bm0 + m) * EDIM + bn0;
#pragma unroll
            for (int in = 0; in < 4; in++) {
                const int n = wn + in * 8 + (lane & 3) * 2;
                float k0 = esq_sh[n]     - 2.0f * acc[im][in][qh * 2 + 0];
                float k1 = esq_sh[n + 1] - 2.0f * acc[im][in][qh * 2 + 1];
                float2 kv = make_float2(k0, k1);
                *(float2*)(krow + n) = kv;
                unsigned long long p0 =
                    ((unsigned long long)ordered_float(k0) << 32) | (unsigned)(bn0 + n);
                unsigned long long p1 =
                    ((unsigned long long)ordered_float(k1) << 32) | (unsigned)(bn0 + n + 1);
                best = p0 < best ? p0 : best;
                best = p1 < best ? p1 : best;
            }
            atomicMin(&best_sh[m], best);
        }
    }
    __syncthreads();
    if (t < BM) atomicMin(&g_best[bm0 + t], best_sh[t]);
}

// ---------------------------------------------------------------------------
// Kernel 3: exact-fp32 rescore of candidates within MARGIN, write one-hot
// grid = BDIM CTAs, 256 threads
// ---------------------------------------------------------------------------
__global__ __launch_bounds__(256)
void vq_rescore_kernel(const float* __restrict__ A, const float* __restrict__ W,
                       float* __restrict__ out) {
    __shared__ int ncand;
    __shared__ int cand[256];
    __shared__ float warp_red[8];
    __shared__ unsigned long long best_sh;

    const int b = blockIdx.x;
    const int t = threadIdx.x;
    if (t == 0) { ncand = 0; best_sh = 0xFFFFFFFFFFFFFFFFULL; }
    __syncthreads();

    unsigned long long packed = g_best[b];
    float thr = inv_ordered((unsigned int)(packed >> 32)) + MARGIN;
    const float* keys = g_keys + (size_t)b * EDIM;
    for (int e = t; e < EDIM; e += 256) {
        if (keys[e] <= thr) {
            int i = atomicAdd(&ncand, 1);
            if (i < 256) cand[i] = e;
        }
    }
    __syncthreads();

    int nc = ncand < 256 ? ncand : 256;
    const float4* x4 = (const float4*)(A + (size_t)b * KDIM);
    for (int ci = 0; ci < nc; ci++) {
        int e = cand[ci];
        const float4* w4 = (const float4*)(W + (size_t)e * KDIM);
        float acc = 0.0f;
#pragma unroll 4
        for (int q = 0; q < 16; q++) {
            float4 w = w4[t + q * 256];
            float4 x = x4[t + q * 256];
            acc += w.x * (w.x - 2.0f * x.x) + w.y * (w.y - 2.0f * x.y)
                 + w.z * (w.z - 2.0f * x.z) + w.w * (w.w - 2.0f * x.w);
        }
#pragma unroll
        for (int o = 16; o > 0; o >>= 1) acc += __shfl_xor_sync(0xffffffffu, acc, o);
        if ((t & 31) == 0) warp_red[t >> 5] = acc;
        __syncthreads();
        if (t == 0) {
            float tot = 0.0f;
#pragma unroll
            for (int w = 0; w < 8; w++) tot += warp_red[w];
            unsigned long long p =
                ((unsigned long long)ordered_float(tot) << 32) | (unsigned int)e;
            if (p < best_sh) best_sh = p;
        }
        __syncthreads();
    }

    if (t == 0) out[(size_t)b * EDIM + (unsigned int)(best_sh & 0xFFFFFFFFu)] = 1.0f;
}

// ---------------------------------------------------------------------------
// Host launch
// ---------------------------------------------------------------------------
extern "C" void kernel_launch(void* const* d_in, const int* in_sizes, int n_in,
                              void* d_out, int out_size) {
    const float* inputs = (const float*)d_in[0];   // [256, 16384]
    const float* codes  = (const float*)d_in[1];   // [4096, 16384]
    float* out = (float*)d_out;                    // [256, 4096]

    cudaFuncSetAttribute(vq_main_kernel,
                         cudaFuncAttributeMaxDynamicSharedMemorySize, DYN_SMEM);

    vq_init_kernel<<<BDIM * EDIM / 4 / 256, 256>>>((float4*)out);

    dim3 grid(EDIM / BN, BDIM / BM);   // (64, 2)
    vq_main_kernel<<<grid, 256, DYN_SMEM>>>(inputs, codes);

    vq_rescore_kernel<<<BDIM, 256>>>(inputs, codes, out);
}

// round 7
// speedup vs baseline: 7.1181x; 1.3273x over previous
#include <cuda_runtime.h>
#include <cuda_bf16.h>
#include <cstdint>

// ---------------------------------------------------------------------------
// Problem constants
// ---------------------------------------------------------------------------
#define BDIM 256      // batch rows
#define EDIM 4096     // codes
#define KDIM 16384    // embedding dim

// GEMM tiling
#define BM 128        // batch rows per CTA
#define BN 64         // codes per CTA
#define BK 64         // k per stage (64 bf16 = 128 B = one SW128 row)
#define NCHUNK (KDIM / BK)                    // 256
#define A_BYTES (BM * BK * 2)                 // 16384
#define B_BYTES (BN * BK * 2)                 // 8192
#define STAGE_BYTES (A_BYTES + B_BYTES)       // 24576
#define NSTAGE 4
#define DYN_SMEM (NSTAGE * STAGE_BYTES + 128) // 98432

#define MARGIN 12.0f

__device__ unsigned long long g_best[BDIM];
__device__ float g_keys[BDIM * EDIM];                     // approx keys (4 MB)
__device__ float g_esq[EDIM];                             // exact ||e||^2
__device__ __nv_bfloat16 g_wb[(size_t)EDIM * KDIM];       // bf16 codebook (128 MB)
__device__ __nv_bfloat16 g_ab[(size_t)BDIM * KDIM];       // bf16 inputs (8 MB)

// ---------------------------------------------------------------------------
// Helpers
// ---------------------------------------------------------------------------
__device__ __forceinline__ uint32_t smem_u32(const void* p) {
    uint32_t a;
    asm("{ .reg .u64 t; cvta.to.shared.u64 t, %1; cvt.u32.u64 %0, t; }" : "=r"(a) : "l"(p));
    return a;
}

#define SW128(o) ((o) ^ (((o) >> 3) & 0x70))

__device__ __forceinline__ unsigned int ordered_float(float f) {
    unsigned int u = __float_as_uint(f);
    return (u & 0x80000000u) ? ~u : (u | 0x80000000u);
}
__device__ __forceinline__ float inv_ordered(unsigned int o) {
    unsigned int u = (o & 0x80000000u) ? (o ^ 0x80000000u) : ~o;
    return __uint_as_float(u);
}

// pack two fp32 -> bf16x2 (lo in low half)
__device__ __forceinline__ uint32_t pk_bf2(float lo, float hi) {
    uint32_t r;
    asm("cvt.rn.bf16x2.f32 %0, %1, %2;" : "=r"(r) : "f"(hi), "f"(lo));
    return r;
}

__device__ __forceinline__ void ldsm4(uint32_t* r, uint32_t addr) {
    asm volatile("ldmatrix.sync.aligned.m8n8.x4.shared.b16 {%0,%1,%2,%3}, [%4];"
                 : "=r"(r[0]), "=r"(r[1]), "=r"(r[2]), "=r"(r[3]) : "r"(addr));
}

__device__ __forceinline__ void mma16816(float* d, const uint32_t* a,
                                         uint32_t b0, uint32_t b1) {
    asm volatile("mma.sync.aligned.m16n8k16.row.col.f32.bf16.bf16.f32 "
                 "{%0,%1,%2,%3}, {%4,%5,%6,%7}, {%8,%9}, {%0,%1,%2,%3};"
                 : "+f"(d[0]), "+f"(d[1]), "+f"(d[2]), "+f"(d[3])
                 : "r"(a[0]), "r"(a[1]), "r"(a[2]), "r"(a[3]), "r"(b0), "r"(b1));
}

__device__ __forceinline__ void cp_async16(uint32_t dst, const void* src) {
    asm volatile("cp.async.cg.shared.global [%0], [%1], 16;"
                 :: "r"(dst), "l"(src) : "memory");
}
#define CP_COMMIT() asm volatile("cp.async.commit_group;" ::: "memory")
#define CP_WAIT2()  asm volatile("cp.async.wait_group 2;" ::: "memory")

// ---------------------------------------------------------------------------
// Kernel 1: init — zero one-hot output, reset per-row best
// ---------------------------------------------------------------------------
__global__ void vq_init_kernel(float4* __restrict__ out4) {
    int i = blockIdx.x * blockDim.x + threadIdx.x;   // BDIM*EDIM/4 threads
    out4[i] = make_float4(0.f, 0.f, 0.f, 0.f);
    if (i < BDIM) g_best[i] = 0xFFFFFFFFFFFFFFFFULL;
}

// ---------------------------------------------------------------------------
// Kernel 2: fp32 -> bf16 conversion pass + exact ||e||^2 per code
// one warp per FULL row: 128 iters x 32 lanes x 4 floats = 16384 = KDIM
// grid = (EDIM + BDIM) / 8 CTAs of 256 threads
// ---------------------------------------------------------------------------
__global__ __launch_bounds__(256)
void vq_convert_kernel(const float* __restrict__ A, const float* __restrict__ W) {
    const int gw   = blockIdx.x * 8 + (threadIdx.x >> 5);
    const int lane = threadIdx.x & 31;

    if (gw < EDIM) {
        const float4* src = (const float4*)(W + (size_t)gw * KDIM);
        __nv_bfloat16* dst = g_wb + (size_t)gw * KDIM;
        float esq = 0.0f;
#pragma unroll 8
        for (int k = 0; k < KDIM / 128; k++) {          // 128 iterations
            float4 v = src[lane + 32 * k];
            esq += v.x * v.x + v.y * v.y + v.z * v.z + v.w * v.w;
            uint2 p = make_uint2(pk_bf2(v.x, v.y), pk_bf2(v.z, v.w));
            *(uint2*)(dst + (size_t)(lane + 32 * k) * 4) = p;
        }
#pragma unroll
        for (int o = 16; o; o >>= 1) esq += __shfl_xor_sync(0xffffffffu, esq, o);
        if (lane == 0) g_esq[gw] = esq;
    } else if (gw < EDIM + BDIM) {
        const int r = gw - EDIM;
        const float4* src = (const float4*)(A + (size_t)r * KDIM);
        __nv_bfloat16* dst = g_ab + (size_t)r * KDIM;
#pragma unroll 8
        for (int k = 0; k < KDIM / 128; k++) {          // 128 iterations
            float4 v = src[lane + 32 * k];
            uint2 p = make_uint2(pk_bf2(v.x, v.y), pk_bf2(v.z, v.w));
            *(uint2*)(dst + (size_t)(lane + 32 * k) * 4) = p;
        }
    }
}

// ---------------------------------------------------------------------------
// Kernel 3: bf16 mma.sync GEMM over pre-converted operands, cp.async 4-stage
// grid (EDIM/BN, BDIM/BM) = (64, 2); 256 threads (8 warps, 32x32 each)
// ---------------------------------------------------------------------------
__global__ __launch_bounds__(256, 1)
void vq_main_kernel() {
    extern __shared__ char dynraw[];
    __shared__ float esq_sh[BN];
    __shared__ unsigned long long best_sh[BM];

    const int t    = threadIdx.x;
    const int lane = t & 31;
    const int wid  = t >> 5;
    const int bn0  = blockIdx.x * BN;
    const int bm0  = blockIdx.y * BM;
    const int wm   = (wid & 3) * 32;
    const int wn   = (wid >> 2) * 32;

    const uint32_t sbase = (smem_u32(dynraw) + 127u) & ~127u;

    if (t < BM) best_sh[t] = 0xFFFFFFFFFFFFFFFFULL;
    if (t < BN) esq_sh[t] = g_esq[bn0 + t];

    float acc[2][4][4];
#pragma unroll
    for (int im = 0; im < 2; im++)
#pragma unroll
        for (int in = 0; in < 4; in++)
#pragma unroll
            for (int q = 0; q < 4; q++) acc[im][in][q] = 0.0f;

    // producer mapping: 1536 16B segments/chunk, 6 per thread.
    // k=0..3 -> A rows (0..127), k=4..5 -> B rows (0..63). No divergence.
    uint32_t doff[6];
    const char* src[6];
#pragma unroll
    for (int k = 0; k < 6; k++) {
        const int seg = t + 256 * k;
        const int row = seg >> 3;
        const int c16 = seg & 7;
        if (row < BM) {
            doff[k] = SW128((uint32_t)(row * 128 + c16 * 16));
            src[k]  = (const char*)(g_ab + (size_t)(bm0 + row) * KDIM + c16 * 8);
        } else {
            const int r = row - BM;
            doff[k] = A_BYTES + SW128((uint32_t)(r * 128 + c16 * 16));
            src[k]  = (const char*)(g_wb + (size_t)(bn0 + r) * KDIM + c16 * 8);
        }
    }

#define ISSUE(c) do {                                                      \
        const uint32_t _st = sbase + (uint32_t)((c) & 3) * STAGE_BYTES;    \
        _Pragma("unroll")                                                  \
        for (int _k = 0; _k < 6; _k++)                                     \
            cp_async16(_st + doff[_k], src[_k] + (size_t)(c) * (BK * 2));  \
    } while (0)

    ISSUE(0); CP_COMMIT();
    ISSUE(1); CP_COMMIT();
    ISSUE(2); CP_COMMIT();

    for (int c = 0; c < NCHUNK; c++) {
        CP_WAIT2();            // chunk c resident (<=2 newer groups pending)
        __syncthreads();       // all threads done computing chunk c-1
        if (c + 3 < NCHUNK) ISSUE(c + 3);   // overwrites stage (c-1)&3: safe
        CP_COMMIT();           // always commit (keeps group arithmetic uniform)

        const uint32_t sA = sbase + (uint32_t)(c & 3) * STAGE_BYTES;
        const uint32_t sB = sA + A_BYTES;

#pragma unroll
        for (int ks = 0; ks < 4; ks++) {
            uint32_t afr[2][4], bfr[2][4];
#pragma unroll
            for (int im = 0; im < 2; im++) {
                const int row = wm + im * 16 + (lane & 15);
                uint32_t off = (uint32_t)(row * 128 + ks * 32 + (lane >> 4) * 16);
                ldsm4(afr[im], sA + SW128(off));
            }
#pragma unroll
            for (int j = 0; j < 2; j++) {
                const int row = wn + 16 * j + (lane & 7) + ((lane >> 4) & 1) * 8;
                uint32_t off = (uint32_t)(row * 128 + ks * 32 + ((lane >> 3) & 1) * 16);
                ldsm4(bfr[j], sB + SW128(off));
            }
#pragma unroll
            for (int im = 0; im < 2; im++)
#pragma unroll
                for (int in = 0; in < 4; in++)
                    mma16816(acc[im][in], afr[im],
                             bfr[in >> 1][(in & 1) * 2],
                             bfr[in >> 1][(in & 1) * 2 + 1]);
        }
    }
#undef ISSUE

    __syncthreads();

    // ---- epilogue: approx keys + per-row packed argmin ----
#pragma unroll
    for (int im = 0; im < 2; im++) {
#pragma unroll
        for (int qh = 0; qh < 2; qh++) {
            const int m = wm + im * 16 + qh * 8 + (lane >> 2);
            unsigned long long best = 0xFFFFFFFFFFFFFFFFULL;
            float* krow = g_keys + (size_t)(bm0 + m) * EDIM + bn0;
#pragma unroll
            for (int in = 0; in < 4; in++) {
                const int n = wn + in * 8 + (lane & 3) * 2;
                float k0 = esq_sh[n]     - 2.0f * acc[im][in][qh * 2 + 0];
                float k1 = esq_sh[n + 1] - 2.0f * acc[im][in][qh * 2 + 1];
                *(float2*)(krow + n) = make_float2(k0, k1);
                unsigned long long p0 =
                    ((unsigned long long)ordered_float(k0) << 32) | (unsigned)(bn0 + n);
                unsigned long long p1 =
                    ((unsigned long long)ordered_float(k1) << 32) | (unsigned)(bn0 + n + 1);
                best = p0 < best ? p0 : best;
                best = p1 < best ? p1 : best;
            }
            atomicMin(&best_sh[m], best);
        }
    }
    __syncthreads();
    if (t < BM) atomicMin(&g_best[bm0 + t], best_sh[t]);
}

// ---------------------------------------------------------------------------
// Kernel 4: exact-fp32 rescore of candidates within MARGIN, write one-hot
// grid = BDIM CTAs, 256 threads
// ---------------------------------------------------------------------------
__global__ __launch_bounds__(256)
void vq_rescore_kernel(const float* __restrict__ A, const float* __restrict__ W,
                       float* __restrict__ out) {
    __shared__ int ncand;
    __shared__ int cand[256];
    __shared__ float warp_red[8];
    __shared__ unsigned long long best_sh;

    const int b = blockIdx.x;
    const int t = threadIdx.x;
    if (t == 0) { ncand = 0; best_sh = 0xFFFFFFFFFFFFFFFFULL; }
    __syncthreads();

    unsigned long long packed = g_best[b];
    float thr = inv_ordered((unsigned int)(packed >> 32)) + MARGIN;
    const float* keys = g_keys + (size_t)b * EDIM;
    for (int e = t; e < EDIM; e += 256) {
        if (keys[e] <= thr) {
            int i = atomicAdd(&ncand, 1);
            if (i < 256) cand[i] = e;
        }
    }
    __syncthreads();

    int nc = ncand < 256 ? ncand : 256;
    const float4* x4 = (const float4*)(A + (size_t)b * KDIM);
    for (int ci = 0; ci < nc; ci++) {
        int e = cand[ci];
        const float4* w4 = (const float4*)(W + (size_t)e * KDIM);
        float acc = 0.0f;
#pragma unroll 4
        for (int q = 0; q < 16; q++) {
            float4 w = w4[t + q * 256];
            float4 x = x4[t + q * 256];
            acc += w.x * (w.x - 2.0f * x.x) + w.y * (w.y - 2.0f * x.y)
                 + w.z * (w.z - 2.0f * x.z) + w.w * (w.w - 2.0f * x.w);
        }
#pragma unroll
        for (int o = 16; o > 0; o >>= 1) acc += __shfl_xor_sync(0xffffffffu, acc, o);
        if ((t & 31) == 0) warp_red[t >> 5] = acc;
        __syncthreads();
        if (t == 0) {
            float tot = 0.0f;
#pragma unroll
            for (int w = 0; w < 8; w++) tot += warp_red[w];
            unsigned long long p =
                ((unsigned long long)ordered_float(tot) << 32) | (unsigned int)e;
            if (p < best_sh) best_sh = p;
        }
        __syncthreads();
    }

    if (t == 0) out[(size_t)b * EDIM + (unsigned int)(best_sh & 0xFFFFFFFFu)] = 1.0f;
}

// ---------------------------------------------------------------------------
// Host launch
// ---------------------------------------------------------------------------
extern "C" void kernel_launch(void* const* d_in, const int* in_sizes, int n_in,
                              void* d_out, int out_size) {
    const float* inputs = (const float*)d_in[0];   // [256, 16384]
    const float* codes  = (const float*)d_in[1];   // [4096, 16384]
    float* out = (float*)d_out;                    // [256, 4096]

    cudaFuncSetAttribute(vq_main_kernel,
                         cudaFuncAttributeMaxDynamicSharedMemorySize, DYN_SMEM);

    vq_init_kernel<<<BDIM * EDIM / 4 / 256, 256>>>((float4*)out);
    vq_convert_kernel<<<(EDIM + BDIM) / 8, 256>>>(inputs, codes);

    dim3 grid(EDIM / BN, BDIM / BM);   // (64, 2)
    vq_main_kernel<<<grid, 256, DYN_SMEM>>>();

    vq_rescore_kernel<<<BDIM, 256>>>(inputs, codes, out);
}